// round 16
// baseline (speedup 1.0000x reference)
#include <cuda_runtime.h>
#include <math.h>

#define BATCH 128
#define SEQ   1024
#define INP   7
#define HID   64
#define OUTD  500
#define MTOT  (BATCH*SEQ)   // 131072
#define HSP   20

typedef unsigned long long u64;
typedef unsigned int u32;

__device__ float g_hT[(size_t)HID * MTOT];   // h transposed: g_hT[k][b*SEQ+t]

// ---- f32x2 packed helpers (lstm) ----
__device__ __forceinline__ u64 pack2(float a, float b) {
    u64 r;
    asm("mov.b64 %0, {%1, %2};" : "=l"(r)
        : "r"(__float_as_uint(a)), "r"(__float_as_uint(b)));
    return r;
}
__device__ __forceinline__ u64 ffma2(u64 a, u64 b, u64 c) {
    u64 d;
    asm("fma.rn.f32x2 %0, %1, %2, %3;" : "=l"(d) : "l"(a), "l"(b), "l"(c));
    return d;
}
__device__ __forceinline__ u64 fadd2(u64 a, u64 b) {
    u64 d;
    asm("add.rn.f32x2 %0, %1, %2;" : "=l"(d) : "l"(a), "l"(b));
    return d;
}
__device__ __forceinline__ void unpack2(u64 v, float& lo, float& hi) {
    u32 l, h;
    asm("mov.b64 {%0, %1}, %2;" : "=r"(l), "=r"(h) : "l"(v));
    lo = __uint_as_float(l); hi = __uint_as_float(h);
}
__device__ __forceinline__ float tanhf_fast(float x) {
    float y;
    asm("tanh.approx.f32 %0, %1;" : "=f"(y) : "f"(x));
    return y;
}
// ---- tf32 / cp.async helpers (fc) ----
__device__ __forceinline__ u32 cvt_tf32(float x) {
    u32 r; asm("cvt.rna.tf32.f32 %0, %1;" : "=r"(r) : "f"(x)); return r;
}
__device__ __forceinline__ void mma_tf32(float* d,
    u32 a0, u32 a1, u32 a2, u32 a3, u32 b0, u32 b1)
{
    asm volatile(
        "mma.sync.aligned.m16n8k8.row.col.f32.tf32.tf32.f32 "
        "{%0,%1,%2,%3}, {%4,%5,%6,%7}, {%8,%9}, {%0,%1,%2,%3};"
        : "+f"(d[0]), "+f"(d[1]), "+f"(d[2]), "+f"(d[3])
        : "r"(a0), "r"(a1), "r"(a2), "r"(a3), "r"(b0), "r"(b1));
}
__device__ __forceinline__ void cp_async16(u32 saddr, const void* gptr) {
    asm volatile("cp.async.cg.shared.global [%0], [%1], 16;"
                 :: "r"(saddr), "l"(gptr));
}
#define CP_COMMIT() asm volatile("cp.async.commit_group;" ::: "memory")
#define CP_WAIT0()  asm volatile("cp.async.wait_group 0;"  ::: "memory")

// ---------------------------------------------------------------------------
// LSTM recurrence: R15 core with two chain-shortening edits:
//  (1) x-contribution folded into the FFMA2 accumulators (x staged stride-8,
//      W_ih packed f32x2, bias seeds chain a0) — removes 7 scalar LDS + the
//      serial 7-FMA chain + 2 adds per step.
//  (2) gate0 stores hbuf, gate1 stores hstage — max 1 pre-barrier STS/thread.
// ---------------------------------------------------------------------------
__global__ __launch_bounds__(256, 1)
void lstm_kernel(const float* __restrict__ x,
                 const float* __restrict__ W_ih,
                 const float* __restrict__ W_hh,
                 const float* __restrict__ b_ih,
                 const float* __restrict__ b_hh)
{
    __shared__ __align__(16) float xsp[SEQ * 8];         // 32 KB (stride-8, padded)
    __shared__ __align__(16) float hbuf[2][HID];
    __shared__ __align__(16) float hstage[2][HID][HSP];  // 10 KB

    const int b    = blockIdx.x;
    const int tid  = threadIdx.x;
    const int hh   = tid >> 2;
    const int gate = tid & 3;
    const int row  = gate * HID + hh;
    const int lane = tid & 31;
    const int lb   = lane & ~3;

    // stage x[b] into stride-8 padded layout (coalesced LDG, scatter STS)
    {
        const float* src = x + (size_t)b * SEQ * INP;
        for (int i = tid; i < SEQ * INP; i += 256) {
            int t = i / INP, k = i - t * INP;
            xsp[t * 8 + k] = src[i];
        }
        for (int i = tid; i < SEQ; i += 256) xsp[i * 8 + 7] = 0.0f;
    }

    // W_hh row -> packed registers
    u64 w2[HID/2];
    {
        const ulonglong2* wr = (const ulonglong2*)(W_hh + (size_t)row * HID);
        #pragma unroll
        for (int i = 0; i < HID/4; ++i) {
            ulonglong2 v = wr[i];
            w2[2*i+0] = v.x; w2[2*i+1] = v.y;
        }
    }
    // W_ih row -> 4 packed f32x2 (8th lane zero), bias packed as a0 seed
    u64 wx[4];
    wx[0] = pack2(W_ih[row*INP+0], W_ih[row*INP+1]);
    wx[1] = pack2(W_ih[row*INP+2], W_ih[row*INP+3]);
    wx[2] = pack2(W_ih[row*INP+4], W_ih[row*INP+5]);
    wx[3] = pack2(W_ih[row*INP+6], 0.0f);
    const u64 bias2 = pack2(b_ih[row] + b_hh[row], 0.0f);

    const float scale = (gate == 2) ? 1.0f : 0.5f;
    const float off   = (gate == 2) ? 0.0f : 0.5f;

    if (tid < HID) hbuf[0][tid] = 0.0f;
    float c = 0.0f;
    __syncthreads();

    int cur = 0;
    for (int t = 0; t < SEQ; ++t) {
        // x-term: 2 broadcast LDS.128 + 4 FFMA2 seeding chains a0..a3
        const ulonglong2* xv = (const ulonglong2*)(xsp + t*8);
        ulonglong2 xA = xv[0];
        ulonglong2 xB = xv[1];

        u64 a0 = ffma2(xA.x, wx[0], bias2);
        u64 a1 = ffma2(xA.y, wx[1], 0ull);
        u64 a2 = ffma2(xB.x, wx[2], 0ull);
        u64 a3 = ffma2(xB.y, wx[3], 0ull);
        u64 a4 = 0ull, a5 = 0ull, a6 = 0ull, a7 = 0ull;

        const ulonglong2* hv = (const ulonglong2*)hbuf[cur];
        #pragma unroll
        for (int j = 0; j < 4; ++j) {
            ulonglong2 h0 = hv[4*j+0];
            ulonglong2 h1 = hv[4*j+1];
            ulonglong2 h2 = hv[4*j+2];
            ulonglong2 h3 = hv[4*j+3];
            a0 = ffma2(h0.x, w2[8*j+0], a0);
            a1 = ffma2(h0.y, w2[8*j+1], a1);
            a2 = ffma2(h1.x, w2[8*j+2], a2);
            a3 = ffma2(h1.y, w2[8*j+3], a3);
            a4 = ffma2(h2.x, w2[8*j+4], a4);
            a5 = ffma2(h2.y, w2[8*j+5], a5);
            a6 = ffma2(h3.x, w2[8*j+6], a6);
            a7 = ffma2(h3.y, w2[8*j+7], a7);
        }
        u64 s0 = fadd2(a0, a1);
        u64 s1 = fadd2(a2, a3);
        u64 s2 = fadd2(a4, a5);
        u64 s3 = fadd2(a6, a7);
        u64 s  = fadd2(fadd2(s0, s1), fadd2(s2, s3));
        float slo, shi; unpack2(s, slo, shi);
        float pre = slo + shi;

        float act = fmaf(scale, tanhf_fast(scale * pre), off);

        float ig = __shfl_sync(0xffffffffu, act, lb+0);
        float fg = __shfl_sync(0xffffffffu, act, lb+1);
        float gg = __shfl_sync(0xffffffffu, act, lb+2);
        float og = __shfl_sync(0xffffffffu, act, lb+3);

        c = fmaf(fg, c, ig*gg);
        float h = og * tanhf_fast(c);
        if (gate == 0) hbuf[cur^1][hh] = h;                      // 1 STS
        if (gate == 1) hstage[(t>>4)&1][hh][t & 15] = h;         // 1 STS

        __syncthreads();
        cur ^= 1;

        if ((t & 15) == 15) {
            int wsel = (t >> 4) & 1;
            int k = tid >> 2;
            int j = (tid & 3) * 4;
            const float* hp = &hstage[wsel][k][j];
            float4 v = make_float4(hp[0], hp[1], hp[2], hp[3]);
            *(float4*)(g_hT + (size_t)k*MTOT + (size_t)b*SEQ + (t-15) + j) = v;
        }
    }
}

// ---------------------------------------------------------------------------
// FC on tensor cores (round-14 proven version, verbatim): tf32 MMA,
// cp.async double-buffered A, raw-fp32 A operands, 2 CTAs/SM.
// ---------------------------------------------------------------------------
#define AST   136
#define MLOOP 8

__global__ __launch_bounds__(256, 2)
void fc_mma_kernel(const float* __restrict__ W_fc,
                   const float* __restrict__ b_fc,
                   float* __restrict__ out)
{
    extern __shared__ u32 smemu[];
    u32*   Abuf[2] = { smemu, smemu + HID*AST };        // 2 x 34816 B
    uint4* Bs4 = (uint4*)(smemu + 2*HID*AST);           // [8][4][32] 16384 B
    float* bs  = (float*)(Bs4 + 8*4*32);                // [64] bias

    const int tid  = threadIdx.x;
    const int lane = tid & 31;
    const int warp = tid >> 5;
    const int lg   = lane >> 2;
    const int lt   = lane & 3;
    const int col0 = blockIdx.y * 64;
    const int ROW0 = blockIdx.x * (128 * MLOOP);

    #pragma unroll
    for (int q = 0; q < 4; ++q) {
        int idx = tid + q*256;
        int bl  = idx & 31;
        int jj  = (idx >> 5) & 3;
        int s   = idx >> 7;
        int kA  = s*8 + (bl & 3);
        int n1  = col0 + jj*16 + (bl >> 2);
        int n2  = n1 + 8;
        float fx=0.f, fy=0.f, fz=0.f, fw=0.f;
        if (n1 < OUTD) { fx = W_fc[n1*HID + kA]; fy = W_fc[n1*HID + kA + 4]; }
        if (n2 < OUTD) { fz = W_fc[n2*HID + kA]; fw = W_fc[n2*HID + kA + 4]; }
        Bs4[(s*4 + jj)*32 + bl] =
            make_uint4(cvt_tf32(fx), cvt_tf32(fy), cvt_tf32(fz), cvt_tf32(fw));
    }
    if (tid < 64) {
        int n = col0 + tid;
        bs[tid] = (n < OUTD) ? b_fc[n] : 0.0f;
    }

    int ak[8];
    #pragma unroll
    for (int l = 0; l < 8; ++l) ak[l] = (tid + l*256) >> 5;
    const int am = (tid & 31) * 4;

    {
        u32 sbase = (u32)__cvta_generic_to_shared(Abuf[0]);
        #pragma unroll
        for (int l = 0; l < 8; ++l)
            cp_async16(sbase + (u32)(ak[l]*AST + am)*4,
                       g_hT + (size_t)ak[l]*MTOT + ROW0 + am);
        CP_COMMIT();
    }

    for (int mt = 0; mt < MLOOP; ++mt) {
        u32* Acur = Abuf[mt & 1];
        u32* Anxt = Abuf[(mt & 1) ^ 1];

        CP_WAIT0();
        __syncthreads();

        if (mt + 1 < MLOOP) {
            u32 sbase = (u32)__cvta_generic_to_shared(Anxt);
            const int rn = ROW0 + (mt+1)*128;
            #pragma unroll
            for (int l = 0; l < 8; ++l)
                cp_async16(sbase + (u32)(ak[l]*AST + am)*4,
                           g_hT + (size_t)ak[l]*MTOT + rn + am);
            CP_COMMIT();
        }

        float d[8][4];
        #pragma unroll
        for (int j = 0; j < 8; ++j)
            #pragma unroll
            for (int p = 0; p < 4; ++p) d[j][p] = 0.f;

        #pragma unroll
        for (int s = 0; s < 8; ++s) {
            const int ka = s*8 + lt;
            const int mb = 16*warp + lg;
            u32 a0 = Acur[ ka      *AST + mb    ];
            u32 a1 = Acur[ ka      *AST + mb + 8];
            u32 a2 = Acur[(ka + 4) *AST + mb    ];
            u32 a3 = Acur[(ka + 4) *AST + mb + 8];
            #pragma unroll
            for (int jj = 0; jj < 4; ++jj) {
                uint4 bb = Bs4[(s*4 + jj)*32 + lane];
                mma_tf32(d[2*jj  ], a0, a1, a2, a3, bb.x, bb.y);
                mma_tf32(d[2*jj+1], a0, a1, a2, a3, bb.z, bb.w);
            }
        }

        const int r0 = ROW0 + mt*128 + 16*warp + lg;
        float* o0 = out + (size_t)r0 * OUTD;
        float* o1 = o0 + 8 * OUTD;
        #pragma unroll
        for (int j = 0; j < 8; ++j) {
            int njl = j*8 + lt*2;
            int nj  = col0 + njl;
            if (nj < OUTD) {
                float bx = bs[njl], by = bs[njl+1];
                float2 v0, v1;
                v0.x = d[j][0] + bx;  v0.y = d[j][1] + by;
                v1.x = d[j][2] + bx;  v1.y = d[j][3] + by;
                *(float2*)(o0 + nj) = v0;
                *(float2*)(o1 + nj) = v1;
            }
        }
        __syncthreads();
    }
}

extern "C" void kernel_launch(void* const* d_in, const int* in_sizes, int n_in,
                              void* d_out, int out_size)
{
    const float* x    = (const float*)d_in[0];
    const float* W_ih = (const float*)d_in[1];
    const float* W_hh = (const float*)d_in[2];
    const float* b_ih = (const float*)d_in[3];
    const float* b_hh = (const float*)d_in[4];
    const float* W_fc = (const float*)d_in[5];
    const float* b_fc = (const float*)d_in[6];
    float* out = (float*)d_out;

    static int smem_set = 0;
    const int dyn = 2*(HID*AST*4) + (8*4*32*16) + 256;   // 86272 B
    if (!smem_set) {
        cudaFuncSetAttribute(fc_mma_kernel,
                             cudaFuncAttributeMaxDynamicSharedMemorySize, dyn);
        smem_set = 1;
    }
    lstm_kernel<<<BATCH, 256>>>(x, W_ih, W_hh, b_ih, b_hh);
    fc_mma_kernel<<<dim3(MTOT/(128*MLOOP), 8), 256, dyn>>>(W_fc, b_fc, out);
}

// round 17
// speedup vs baseline: 1.0307x; 1.0307x over previous
#include <cuda_runtime.h>
#include <math.h>

#define BATCH 128
#define SEQ   1024
#define INP   7
#define HID   64
#define OUTD  500
#define MTOT  (BATCH*SEQ)   // 131072
#define HSP   20

typedef unsigned long long u64;
typedef unsigned int u32;

__device__ float g_hT[(size_t)HID * MTOT];   // h transposed: g_hT[k][b*SEQ+t]

// ---- f32x2 packed helpers (lstm) ----
__device__ __forceinline__ u64 ffma2(u64 a, u64 b, u64 c) {
    u64 d;
    asm("fma.rn.f32x2 %0, %1, %2, %3;" : "=l"(d) : "l"(a), "l"(b), "l"(c));
    return d;
}
__device__ __forceinline__ u64 fadd2(u64 a, u64 b) {
    u64 d;
    asm("add.rn.f32x2 %0, %1, %2;" : "=l"(d) : "l"(a), "l"(b));
    return d;
}
__device__ __forceinline__ void unpack2(u64 v, float& lo, float& hi) {
    u32 l, h;
    asm("mov.b64 {%0, %1}, %2;" : "=r"(l), "=r"(h) : "l"(v));
    lo = __uint_as_float(l); hi = __uint_as_float(h);
}
__device__ __forceinline__ float tanhf_fast(float x) {
    float y;
    asm("tanh.approx.f32 %0, %1;" : "=f"(y) : "f"(x));
    return y;
}
// ---- tf32 / cp.async helpers (fc) ----
__device__ __forceinline__ u32 cvt_tf32(float x) {
    u32 r; asm("cvt.rna.tf32.f32 %0, %1;" : "=r"(r) : "f"(x)); return r;
}
__device__ __forceinline__ void mma_tf32(float* d,
    u32 a0, u32 a1, u32 a2, u32 a3, u32 b0, u32 b1)
{
    asm volatile(
        "mma.sync.aligned.m16n8k8.row.col.f32.tf32.tf32.f32 "
        "{%0,%1,%2,%3}, {%4,%5,%6,%7}, {%8,%9}, {%0,%1,%2,%3};"
        : "+f"(d[0]), "+f"(d[1]), "+f"(d[2]), "+f"(d[3])
        : "r"(a0), "r"(a1), "r"(a2), "r"(a3), "r"(b0), "r"(b1));
}
__device__ __forceinline__ void cp_async16(u32 saddr, const void* gptr) {
    asm volatile("cp.async.cg.shared.global [%0], [%1], 16;"
                 :: "r"(saddr), "l"(gptr));
}
#define CP_COMMIT() asm volatile("cp.async.commit_group;" ::: "memory")
#define CP_WAIT0()  asm volatile("cp.async.wait_group 0;"  ::: "memory")

// ---------------------------------------------------------------------------
// LSTM recurrence (round-15 proven core, verbatim): one CTA per batch,
// 256 threads; xacc computed at the TOP of each iteration.
// ---------------------------------------------------------------------------
__global__ __launch_bounds__(256, 1)
void lstm_kernel(const float* __restrict__ x,
                 const float* __restrict__ W_ih,
                 const float* __restrict__ W_hh,
                 const float* __restrict__ b_ih,
                 const float* __restrict__ b_hh)
{
    __shared__ float xs[SEQ * INP];                      // 28 KB
    __shared__ __align__(16) float hbuf[2][HID];
    __shared__ __align__(16) float hstage[2][HID][HSP];  // 10 KB

    const int b    = blockIdx.x;
    const int tid  = threadIdx.x;
    const int hh   = tid >> 2;
    const int gate = tid & 3;
    const int row  = gate * HID + hh;
    const int lane = tid & 31;
    const int lb   = lane & ~3;

    {
        const float4* src = (const float4*)(x + (size_t)b * SEQ * INP);
        float4* dst = (float4*)xs;
        #pragma unroll
        for (int i = 0; i < (SEQ*INP)/(4*256); ++i)
            dst[tid + i*256] = src[tid + i*256];
    }

    u64 w2[HID/2];
    {
        const ulonglong2* wr = (const ulonglong2*)(W_hh + (size_t)row * HID);
        #pragma unroll
        for (int i = 0; i < HID/4; ++i) {
            ulonglong2 v = wr[i];
            w2[2*i+0] = v.x; w2[2*i+1] = v.y;
        }
    }
    float wih[INP];
    #pragma unroll
    for (int i = 0; i < INP; ++i) wih[i] = W_ih[row*INP + i];
    const float bias = b_ih[row] + b_hh[row];

    const float scale = (gate == 2) ? 1.0f : 0.5f;
    const float off   = (gate == 2) ? 0.0f : 0.5f;

    if (tid < HID) hbuf[0][tid] = 0.0f;
    float c = 0.0f;
    __syncthreads();

    int cur = 0;
    for (int t = 0; t < SEQ; ++t) {
        const float* xt = xs + t*INP;
        float xacc = bias;
        #pragma unroll
        for (int i = 0; i < INP; ++i) xacc = fmaf(xt[i], wih[i], xacc);

        const ulonglong2* hv = (const ulonglong2*)hbuf[cur];
        u64 a[8];
        #pragma unroll
        for (int i = 0; i < 8; ++i) a[i] = 0ull;
        #pragma unroll
        for (int j = 0; j < 4; ++j) {
            ulonglong2 h0 = hv[4*j+0];
            ulonglong2 h1 = hv[4*j+1];
            ulonglong2 h2 = hv[4*j+2];
            ulonglong2 h3 = hv[4*j+3];
            a[0] = ffma2(h0.x, w2[8*j+0], a[0]);
            a[1] = ffma2(h0.y, w2[8*j+1], a[1]);
            a[2] = ffma2(h1.x, w2[8*j+2], a[2]);
            a[3] = ffma2(h1.y, w2[8*j+3], a[3]);
            a[4] = ffma2(h2.x, w2[8*j+4], a[4]);
            a[5] = ffma2(h2.y, w2[8*j+5], a[5]);
            a[6] = ffma2(h3.x, w2[8*j+6], a[6]);
            a[7] = ffma2(h3.y, w2[8*j+7], a[7]);
        }
        u64 s0 = fadd2(a[0], a[1]);
        u64 s1 = fadd2(a[2], a[3]);
        u64 s2 = fadd2(a[4], a[5]);
        u64 s3 = fadd2(a[6], a[7]);
        u64 s  = fadd2(fadd2(s0, s1), fadd2(s2, s3));
        float slo, shi; unpack2(s, slo, shi);
        float pre = xacc + slo + shi;

        float act = fmaf(scale, tanhf_fast(scale * pre), off);

        float ig = __shfl_sync(0xffffffffu, act, lb+0);
        float fg = __shfl_sync(0xffffffffu, act, lb+1);
        float gg = __shfl_sync(0xffffffffu, act, lb+2);
        float og = __shfl_sync(0xffffffffu, act, lb+3);

        c = fmaf(fg, c, ig*gg);
        float h = og * tanhf_fast(c);
        if (gate == 0) {
            hbuf[cur^1][hh] = h;
            hstage[(t>>4)&1][hh][t & 15] = h;
        }

        __syncthreads();
        cur ^= 1;

        if ((t & 15) == 15) {
            int wsel = (t >> 4) & 1;
            int k = tid >> 2;
            int j = (tid & 3) * 4;
            const float* hp = &hstage[wsel][k][j];
            float4 v = make_float4(hp[0], hp[1], hp[2], hp[3]);
            *(float4*)(g_hT + (size_t)k*MTOT + (size_t)b*SEQ + (t-15) + j) = v;
        }
    }
}

// ---------------------------------------------------------------------------
// FC on tensor cores, A-stage-once structure: one CTA per 128-row window
// (grid = 1024). A staged ONCE via cp.async (raw fp32 -> tf32 truncation,
// proven); loop over 8 B fragment tiles (W_fc L2-resident, rna cvt path,
// same fragment code as R13/R14). Cuts A global traffic 8x.
// ---------------------------------------------------------------------------
#define AST 136

__global__ __launch_bounds__(256, 2)
void fc_mma_kernel(const float* __restrict__ W_fc,
                   const float* __restrict__ b_fc,
                   float* __restrict__ out)
{
    extern __shared__ u32 smemu[];
    u32*   As  = smemu;                          // [64][AST] raw fp32, 34816 B
    uint4* Bs4 = (uint4*)(smemu + HID*AST);      // [8][4][32] fragments, 16384 B

    const int tid  = threadIdx.x;
    const int lane = tid & 31;
    const int warp = tid >> 5;
    const int lg   = lane >> 2;
    const int lt   = lane & 3;
    const int ROW0 = blockIdx.x * 128;

    // ---- stage A once via cp.async (raw fp32 bits) ----
    int ak[8];
    #pragma unroll
    for (int l = 0; l < 8; ++l) ak[l] = (tid + l*256) >> 5;   // k row 0..63
    const int am = (tid & 31) * 4;
    {
        u32 sbase = (u32)__cvta_generic_to_shared(As);
        #pragma unroll
        for (int l = 0; l < 8; ++l)
            cp_async16(sbase + (u32)(ak[l]*AST + am)*4,
                       g_hT + (size_t)ak[l]*MTOT + ROW0 + am);
        CP_COMMIT();
    }
    CP_WAIT0();
    __syncthreads();            // A visible to all threads

    for (int nt = 0; nt < 8; ++nt) {
        const int col0 = nt * 64;

        __syncthreads();        // prev tile's B reads done
        // ---- stage B fragments for this 64-col tile (rna cvt, L2-hot) ----
        #pragma unroll
        for (int q = 0; q < 4; ++q) {
            int idx = tid + q*256;
            int bl  = idx & 31;
            int jj  = (idx >> 5) & 3;
            int s   = idx >> 7;
            int kA  = s*8 + (bl & 3);
            int n1  = col0 + jj*16 + (bl >> 2);
            int n2  = n1 + 8;
            float fx=0.f, fy=0.f, fz=0.f, fw=0.f;
            if (n1 < OUTD) { fx = W_fc[n1*HID + kA]; fy = W_fc[n1*HID + kA + 4]; }
            if (n2 < OUTD) { fz = W_fc[n2*HID + kA]; fw = W_fc[n2*HID + kA + 4]; }
            Bs4[(s*4 + jj)*32 + bl] =
                make_uint4(cvt_tf32(fx), cvt_tf32(fy), cvt_tf32(fz), cvt_tf32(fw));
        }
        __syncthreads();

        float d[8][4];
        #pragma unroll
        for (int j = 0; j < 8; ++j)
            #pragma unroll
            for (int p = 0; p < 4; ++p) d[j][p] = 0.f;

        #pragma unroll
        for (int s = 0; s < 8; ++s) {
            const int ka = s*8 + lt;
            const int mb = 16*warp + lg;
            u32 a0 = As[ ka      *AST + mb    ];
            u32 a1 = As[ ka      *AST + mb + 8];
            u32 a2 = As[(ka + 4) *AST + mb    ];
            u32 a3 = As[(ka + 4) *AST + mb + 8];
            #pragma unroll
            for (int jj = 0; jj < 4; ++jj) {
                uint4 bb = Bs4[(s*4 + jj)*32 + lane];
                mma_tf32(d[2*jj  ], a0, a1, a2, a3, bb.x, bb.y);
                mma_tf32(d[2*jj+1], a0, a1, a2, a3, bb.z, bb.w);
            }
        }

        // epilogue: d[j] = rows (r0, r0+8), cols (nj, nj+1); bias L1-hot
        const int r0 = ROW0 + 16*warp + lg;
        float* o0 = out + (size_t)r0 * OUTD;
        float* o1 = o0 + 8 * OUTD;
        #pragma unroll
        for (int j = 0; j < 8; ++j) {
            int nj = col0 + j*8 + lt*2;
            if (nj < OUTD) {
                float bx = b_fc[nj], by = b_fc[nj+1];
                float2 v0, v1;
                v0.x = d[j][0] + bx;  v0.y = d[j][1] + by;
                v1.x = d[j][2] + bx;  v1.y = d[j][3] + by;
                *(float2*)(o0 + nj) = v0;
                *(float2*)(o1 + nj) = v1;
            }
        }
    }
}

extern "C" void kernel_launch(void* const* d_in, const int* in_sizes, int n_in,
                              void* d_out, int out_size)
{
    const float* x    = (const float*)d_in[0];
    const float* W_ih = (const float*)d_in[1];
    const float* W_hh = (const float*)d_in[2];
    const float* b_ih = (const float*)d_in[3];
    const float* b_hh = (const float*)d_in[4];
    const float* W_fc = (const float*)d_in[5];
    const float* b_fc = (const float*)d_in[6];
    float* out = (float*)d_out;

    static int smem_set = 0;
    const int dyn = (HID*AST*4) + (8*4*32*16);   // 34816 + 16384 = 51200 B
    if (!smem_set) {
        cudaFuncSetAttribute(fc_mma_kernel,
                             cudaFuncAttributeMaxDynamicSharedMemorySize, dyn);
        smem_set = 1;
    }
    lstm_kernel<<<BATCH, 256>>>(x, W_ih, W_hh, b_ih, b_hh);
    fc_mma_kernel<<<MTOT/128, 256, dyn>>>(W_fc, b_fc, out);
}